// round 1
// baseline (speedup 1.0000x reference)
#include <cuda_runtime.h>

// actor_53781580480512: per-pair micro-MLP
//   B=4096, Z=64, P=Z*Z=4096, H=4
//   pair(b,p=(z,zp)) = (x[b,z], x[b,zp])
//   h1 = LN(tanh(pair @ W1[p] + b1[p]); g1,be1)
//   h2 = LN(tanh(h1  @ W2[p] + b2[p]); g2,be2)
//   out[b,p] = sigmoid(h2 . W3[p] + b3[p])
//
// Block = (z, b-tile). 256 threads = 64 zp-lanes x 4 b-groups.
// Each thread owns one p, keeps all 53 weight floats in registers,
// loops over 32 b values. Coalesced x reads and out writes.

#define ZDIM 64
#define PDIM 4096
#define BTILE 128

__device__ __forceinline__ float fast_tanh(float x) {
    // tanh(x) = 1 - 2/(exp(2x)+1); EX2-based, abs err ~1e-7
    float e = __expf(x + x);
    return 1.0f - __fdividef(2.0f, e + 1.0f);
}

__device__ __forceinline__ float fast_sigmoid(float x) {
    float e = __expf(-x);
    return __fdividef(1.0f, 1.0f + e);
}

__global__ __launch_bounds__(256)
void actor_mlp_kernel(
    const float* __restrict__ x,
    const float* __restrict__ W1, const float* __restrict__ b1,
    const float* __restrict__ g1, const float* __restrict__ be1,
    const float* __restrict__ W2, const float* __restrict__ b2,
    const float* __restrict__ g2, const float* __restrict__ be2,
    const float* __restrict__ W3, const float* __restrict__ b3,
    float* __restrict__ out, int B)
{
    const int zp = threadIdx.x & 63;        // 0..63
    const int bl = threadIdx.x >> 6;        // 0..3
    const int z  = blockIdx.x;              // 0..63
    const int b0 = blockIdx.y * BTILE;
    const int p  = z * ZDIM + zp;

    // ---- load per-p weights into registers (amortized over BTILE/4 iters) ----
    float w1[8];
#pragma unroll
    for (int i = 0; i < 8; i++) w1[i] = __ldg(&W1[p * 8 + i]);
    float bb1[4], gg1[4], bbe1[4];
#pragma unroll
    for (int i = 0; i < 4; i++) {
        bb1[i]  = __ldg(&b1 [p * 4 + i]);
        gg1[i]  = __ldg(&g1 [p * 4 + i]);
        bbe1[i] = __ldg(&be1[p * 4 + i]);
    }
    float w2[16];
#pragma unroll
    for (int i = 0; i < 16; i++) w2[i] = __ldg(&W2[p * 16 + i]);
    float bb2[4], gg2[4], bbe2[4], w3[4];
#pragma unroll
    for (int i = 0; i < 4; i++) {
        bb2[i]  = __ldg(&b2 [p * 4 + i]);
        gg2[i]  = __ldg(&g2 [p * 4 + i]);
        bbe2[i] = __ldg(&be2[p * 4 + i]);
        w3[i]   = __ldg(&W3 [p * 4 + i]);
    }
    const float bb3 = __ldg(&b3[p]);

    // ---- b loop: warp-uniform b, coalesced x/out access ----
#pragma unroll 2
    for (int it = 0; it < BTILE / 4; it++) {
        const int b = b0 + bl + 4 * it;
        if (b >= B) break;
        const float xa = __ldg(&x[b * ZDIM + z]);   // pair[0] (warp-uniform)
        const float xc = __ldg(&x[b * ZDIM + zp]);  // pair[1] (coalesced)

        // layer 1: h = a*W1[0,:] + c*W1[1,:] + b1
        float h[4];
#pragma unroll
        for (int j = 0; j < 4; j++)
            h[j] = fmaf(xa, w1[j], fmaf(xc, w1[4 + j], bb1[j]));

#pragma unroll
        for (int j = 0; j < 4; j++) h[j] = fast_tanh(h[j]);

        // LayerNorm 1 (biased var, eps inside rsqrt)
        {
            float m = (h[0] + h[1] + h[2] + h[3]) * 0.25f;
            float d0 = h[0] - m, d1 = h[1] - m, d2 = h[2] - m, d3 = h[3] - m;
            float v = fmaf(d0, d0, fmaf(d1, d1, fmaf(d2, d2, d3 * d3))) * 0.25f;
            float r = rsqrtf(v + 1e-5f);
            h[0] = fmaf(d0 * r, gg1[0], bbe1[0]);
            h[1] = fmaf(d1 * r, gg1[1], bbe1[1]);
            h[2] = fmaf(d2 * r, gg1[2], bbe1[2]);
            h[3] = fmaf(d3 * r, gg1[3], bbe1[3]);
        }

        // layer 2: k_j = sum_i h_i * W2[i,j] + b2_j
        float k[4];
#pragma unroll
        for (int j = 0; j < 4; j++) {
            float s = bb2[j];
#pragma unroll
            for (int i = 0; i < 4; i++)
                s = fmaf(h[i], w2[i * 4 + j], s);
            k[j] = s;
        }

#pragma unroll
        for (int j = 0; j < 4; j++) k[j] = fast_tanh(k[j]);

        // LayerNorm 2
        {
            float m = (k[0] + k[1] + k[2] + k[3]) * 0.25f;
            float d0 = k[0] - m, d1 = k[1] - m, d2 = k[2] - m, d3 = k[3] - m;
            float v = fmaf(d0, d0, fmaf(d1, d1, fmaf(d2, d2, d3 * d3))) * 0.25f;
            float r = rsqrtf(v + 1e-5f);
            k[0] = fmaf(d0 * r, gg2[0], bbe2[0]);
            k[1] = fmaf(d1 * r, gg2[1], bbe2[1]);
            k[2] = fmaf(d2 * r, gg2[2], bbe2[2]);
            k[3] = fmaf(d3 * r, gg2[3], bbe2[3]);
        }

        // layer 3 + sigmoid
        float o = bb3;
#pragma unroll
        for (int i = 0; i < 4; i++) o = fmaf(k[i], w3[i], o);
        o = fast_sigmoid(o);

        out[b * PDIM + p] = o;
    }
}

extern "C" void kernel_launch(void* const* d_in, const int* in_sizes, int n_in,
                              void* d_out, int out_size)
{
    const float* x   = (const float*)d_in[0];
    const float* W1  = (const float*)d_in[1];
    const float* b1  = (const float*)d_in[2];
    const float* g1  = (const float*)d_in[3];
    const float* be1 = (const float*)d_in[4];
    const float* W2  = (const float*)d_in[5];
    const float* b2  = (const float*)d_in[6];
    const float* g2  = (const float*)d_in[7];
    const float* be2 = (const float*)d_in[8];
    const float* W3  = (const float*)d_in[9];
    const float* b3  = (const float*)d_in[10];
    float* out = (float*)d_out;

    int B = in_sizes[0] / ZDIM;               // 4096
    dim3 grid(ZDIM, (B + BTILE - 1) / BTILE); // 64 x 32
    actor_mlp_kernel<<<grid, 256>>>(x, W1, b1, g1, be1, W2, b2, g2, be2,
                                    W3, b3, out, B);
}

// round 2
// speedup vs baseline: 1.5757x; 1.5757x over previous
#include <cuda_runtime.h>

// actor_53781580480512 R2: per-pair micro-MLP, MUFU.TANH + LN-folding + ILP2
//   B=4096, Z=64, P=4096, H=4
//
// Folding (precomputed once per launch into __device__ scratch):
//   W2f[p,i,j] = g1[p,i] * W2[p,i,j]
//   b2f[p,j]   = b2[p,j] + sum_i be1[p,i] * W2[p,i,j]
//   W3f[p,j]   = g2[p,j] * W3[p,j]
//   b3f[p]     = b3[p]   + sum_j be2[p,j] * W3[p,j]
// Then per element:
//   h  = tanh(pair @ W1 + b1);  d = h - mean;  r = rsqrt(var+eps)
//   k  = tanh(r * (d @ W2f) + b2f);  e = k - mean2;  r2 = rsqrt(var2+eps)
//   o  = sigmoid(r2 * (e . W3f) + b3f)   [sigmoid = 0.5*tanh(0.5x)+0.5]

#define ZDIM 64
#define PDIM 4096
#define BTILE 128
#define ILP 2

__device__ float g_W2f[PDIM * 16];
__device__ float g_b2f[PDIM * 4];
__device__ float g_W3f[PDIM * 4];
__device__ float g_b3f[PDIM];

__device__ __forceinline__ float tanh_mufu(float x) {
    float y;
    asm("tanh.approx.f32 %0, %1;" : "=f"(y) : "f"(x));
    return y;
}

__global__ void fold_kernel(
    const float* __restrict__ g1, const float* __restrict__ be1,
    const float* __restrict__ W2, const float* __restrict__ b2,
    const float* __restrict__ g2, const float* __restrict__ be2,
    const float* __restrict__ W3, const float* __restrict__ b3)
{
    int p = blockIdx.x * blockDim.x + threadIdx.x;
    if (p >= PDIM) return;
    float gg1[4], bbe1[4];
#pragma unroll
    for (int i = 0; i < 4; i++) { gg1[i] = g1[p*4+i]; bbe1[i] = be1[p*4+i]; }
#pragma unroll
    for (int j = 0; j < 4; j++) {
        float acc = b2[p*4+j];
#pragma unroll
        for (int i = 0; i < 4; i++) {
            float w = W2[p*16 + i*4 + j];
            g_W2f[p*16 + i*4 + j] = gg1[i] * w;
            acc = fmaf(bbe1[i], w, acc);
        }
        g_b2f[p*4+j] = acc;
    }
    float acc3 = b3[p];
#pragma unroll
    for (int j = 0; j < 4; j++) {
        float w = W3[p*4+j];
        g_W3f[p*4+j] = g2[p*4+j] * w;
        acc3 = fmaf(be2[p*4+j], w, acc3);
    }
    g_b3f[p] = acc3;
}

__global__ __launch_bounds__(256)
void actor_mlp_kernel(
    const float* __restrict__ x,
    const float* __restrict__ W1, const float* __restrict__ b1,
    float* __restrict__ out, int B)
{
    const int zp = threadIdx.x & 63;        // 0..63
    const int bl = threadIdx.x >> 6;        // 0..3
    const int z  = blockIdx.x;              // 0..63
    const int b0 = blockIdx.y * BTILE;
    const int p  = z * ZDIM + zp;

    // ---- per-p weights in registers (37 floats) ----
    float w1[8];
#pragma unroll
    for (int i = 0; i < 8; i++) w1[i] = __ldg(&W1[p * 8 + i]);
    float bb1[4];
#pragma unroll
    for (int i = 0; i < 4; i++) bb1[i] = __ldg(&b1[p * 4 + i]);
    float w2[16];
#pragma unroll
    for (int i = 0; i < 16; i++) w2[i] = g_W2f[p * 16 + i];
    float bb2[4], w3[4];
#pragma unroll
    for (int i = 0; i < 4; i++) {
        bb2[i] = g_b2f[p * 4 + i];
        w3[i]  = g_W3f[p * 4 + i];
    }
    const float bb3 = g_b3f[p];

    // ---- b loop: ILP elements in flight per thread ----
#pragma unroll 2
    for (int it = 0; it < BTILE / (4 * ILP); it++) {
        const int bb = b0 + (bl * ILP) + it * (4 * ILP);

        float o[ILP];
#pragma unroll
        for (int u = 0; u < ILP; u++) {
            const int b = bb + u;
            const float xa = __ldg(&x[b * ZDIM + z]);
            const float xc = __ldg(&x[b * ZDIM + zp]);

            // layer 1 + tanh
            float h[4];
#pragma unroll
            for (int j = 0; j < 4; j++)
                h[j] = tanh_mufu(fmaf(xa, w1[j], fmaf(xc, w1[4 + j], bb1[j])));

            // LN1 stats (g/be folded downstream)
            float m = (h[0] + h[1] + h[2] + h[3]) * 0.25f;
            float d0 = h[0] - m, d1 = h[1] - m, d2 = h[2] - m, d3 = h[3] - m;
            float s = fmaf(d0, d0, fmaf(d1, d1, fmaf(d2, d2, d3 * d3)));
            float r = rsqrtf(fmaf(s, 0.25f, 1e-5f));

            // layer 2: k_j = r * (d @ W2f)_j + b2f_j, tanh
            float k[4];
#pragma unroll
            for (int j = 0; j < 4; j++) {
                float dot = d0 * w2[j];
                dot = fmaf(d1, w2[4 + j], dot);
                dot = fmaf(d2, w2[8 + j], dot);
                dot = fmaf(d3, w2[12 + j], dot);
                k[j] = tanh_mufu(fmaf(r, dot, bb2[j]));
            }

            // LN2 stats
            float m2 = (k[0] + k[1] + k[2] + k[3]) * 0.25f;
            float e0 = k[0] - m2, e1 = k[1] - m2, e2 = k[2] - m2, e3 = k[3] - m2;
            float s2 = fmaf(e0, e0, fmaf(e1, e1, fmaf(e2, e2, e3 * e3)));
            float r2 = rsqrtf(fmaf(s2, 0.25f, 1e-5f));

            // layer 3 + sigmoid(x) = 0.5*tanh(0.5x)+0.5
            float dot3 = e0 * w3[0];
            dot3 = fmaf(e1, w3[1], dot3);
            dot3 = fmaf(e2, w3[2], dot3);
            dot3 = fmaf(e3, w3[3], dot3);
            float pre = fmaf(r2, dot3, bb3);
            o[u] = fmaf(0.5f, tanh_mufu(0.5f * pre), 0.5f);
        }

#pragma unroll
        for (int u = 0; u < ILP; u++)
            out[(bb + u) * PDIM + p] = o[u];
    }
}

extern "C" void kernel_launch(void* const* d_in, const int* in_sizes, int n_in,
                              void* d_out, int out_size)
{
    const float* x   = (const float*)d_in[0];
    const float* W1  = (const float*)d_in[1];
    const float* b1  = (const float*)d_in[2];
    const float* g1  = (const float*)d_in[3];
    const float* be1 = (const float*)d_in[4];
    const float* W2  = (const float*)d_in[5];
    const float* b2  = (const float*)d_in[6];
    const float* g2  = (const float*)d_in[7];
    const float* be2 = (const float*)d_in[8];
    const float* W3  = (const float*)d_in[9];
    const float* b3  = (const float*)d_in[10];
    float* out = (float*)d_out;

    int B = in_sizes[0] / ZDIM;

    fold_kernel<<<PDIM / 256, 256>>>(g1, be1, W2, b2, g2, be2, W3, b3);

    dim3 grid(ZDIM, (B + BTILE - 1) / BTILE);
    actor_mlp_kernel<<<grid, 256>>>(x, W1, b1, out, B);
}